// round 14
// baseline (speedup 1.0000x reference)
#include <cuda_runtime.h>
#include <cuda_fp16.h>
#include <math.h>

#define VV 16
#define BB 64
#define TT 256
#define HH 128
#define GG 384
#define FCN 256
#define CC 10
#define NB 8            // batch rows per CTA = MMA N
#define NTHR 256        // 8 warps; warp w owns j-range [16w, 16w+16) for ALL 3 gates
#define NCTA 128

// ---- smem byte offsets ----
#define OFF_WHI 0                        // W_hi fp16 [384][128] swizzled (reused as const table)
#define OFF_H   (OFF_WHI + GG*256)       // 98304: h_q fp16 tiles, 2 parity bufs x 4KB
#define OFF_X   (OFF_H + 2*4096)         // 106496: x f32 [8][256] (reused as hfin / fc scratch)
#define SMEM_TOT (OFF_X + NB*TT*4)       // 114688

typedef unsigned int u32;

__device__ float g_concat[BB * VV];
__device__ int g_ctr = 0;
__device__ int g_ctr2 = 0;

// XOR-swizzled byte offset within a [rows][128] 16-bit tile (256B rows, 16B chunks)
__device__ __forceinline__ int swz(int r, int k) {
    return r * 256 + ((((k >> 3) ^ (r & 7)) & 15) << 4) + ((k & 7) << 1);
}

__device__ __forceinline__ u32 smem_u32(const void* p) {
    u32 a;
    asm("{ .reg .u64 t; cvta.to.shared.u64 t, %1; cvt.u32.u64 %0, t; }" : "=r"(a) : "l"(p));
    return a;
}

__device__ __forceinline__ void ldsm4(u32& a0, u32& a1, u32& a2, u32& a3, u32 addr) {
    asm volatile("ldmatrix.sync.aligned.m8n8.x4.shared.b16 {%0,%1,%2,%3}, [%4];"
                 : "=r"(a0), "=r"(a1), "=r"(a2), "=r"(a3) : "r"(addr));
}
__device__ __forceinline__ void mma16816(float* d, const u32* a, u32 b0, u32 b1) {
    asm volatile("mma.sync.aligned.m16n8k16.row.col.f32.f16.f16.f32 "
                 "{%0,%1,%2,%3}, {%4,%5,%6,%7}, {%8,%9}, {%0,%1,%2,%3};"
                 : "+f"(d[0]), "+f"(d[1]), "+f"(d[2]), "+f"(d[3])
                 : "r"(a[0]), "r"(a[1]), "r"(a[2]), "r"(a[3]), "r"(b0), "r"(b1));
}

__device__ __forceinline__ float tanha_(float x) {
    float y;
    asm("tanh.approx.f32 %0, %1;" : "=f"(y) : "f"(x));
    return y;
}
__device__ __forceinline__ float sigm_(float x) {
    return fmaf(0.5f, tanha_(0.5f * x), 0.5f);
}

__global__ __launch_bounds__(NTHR, 1)
void gru_kernel(const float* __restrict__ x,   const float* __restrict__ Wih,
                const float* __restrict__ Whh, const float* __restrict__ bih,
                const float* __restrict__ bhh, const float* __restrict__ Wp,
                const float* __restrict__ bp,  const float* __restrict__ W1,
                const float* __restrict__ b1,  const float* __restrict__ W2,
                const float* __restrict__ b2,  float* __restrict__ out)
{
    extern __shared__ char sm[];
    const u32 smb = smem_u32(sm);
    const int tid = threadIdx.x;
    const int v  = blockIdx.x >> 3;          // 16 variables
    const int b0g = (blockIdx.x & 7) * NB;   // 8 batch-groups of 8

    // ---- stage Whh[v] as fp16 into swizzled tile ----
    const float* Whh_v = Whh + (size_t)v * GG * HH;
    for (int idx = tid; idx < GG * HH; idx += NTHR) {
        int g = idx >> 7, k = idx & 127;
        *(__half*)(sm + OFF_WHI + swz(g, k)) = __float2half_rn(Whh_v[idx]);
    }
    // ---- zero h parity-buffer 0; buffer 1 fully written at t=0 ----
    for (int idx = tid; idx < 4096 / 4; idx += NTHR)
        ((u32*)(sm + OFF_H))[idx] = 0u;
    // ---- stage x slice ----
    float* sXf = (float*)(sm + OFF_X);
    const float* x_v = x + (size_t)(v * BB + b0g) * TT;
    for (int idx = tid; idx < NB * TT; idx += NTHR) sXf[idx] = x_v[idx];

    // ---- lane geometry ----
    const int w = tid >> 5, L = tid & 31;
    const int rowl  = ((L >> 3) & 1) * 8 + (L & 7);  // A frag row within 16-tile
    const int khalf = (L >> 4) & 1;
    const int xr    = L & 7;
    const int nrow = L & 7;
    const int bg   = (L >> 3) & 3;
    const int quad = L >> 2, qc = L & 3;
    const int j0 = 16 * w + quad, j1 = j0 + 8;       // this lane's j rows
    const int c0 = 2 * qc, c1 = 2 * qc + 1;          // this lane's b cols

    __syncthreads();

    // ---- preload A fragments: all 3 gates, W_hi only (1-term fp16) ----
    u32 ar_h[8][4], az_h[8][4], an_h[8][4];
    {
        const u32 aR = smb + OFF_WHI + (u32)(16 * w + rowl) * 256;           // gate r
        const u32 aZ = aR + 128 * 256;                                        // gate z
        const u32 aN = aR + 256 * 256;                                        // gate n
        #pragma unroll
        for (int s = 0; s < 8; s++) {
            const u32 ca = (u32)((((2 * s + khalf) ^ xr) & 15) << 4);
            ldsm4(ar_h[s][0], ar_h[s][1], ar_h[s][2], ar_h[s][3], aR + ca);
            ldsm4(az_h[s][0], az_h[s][1], az_h[s][2], az_h[s][3], aZ + ca);
            ldsm4(an_h[s][0], an_h[s][1], an_h[s][2], an_h[s][3], aN + ca);
        }
    }
    __syncthreads();

    // ---- gate constants (register-resident, 2 j values) via smem bounce ----
    float* sPC = (float*)(sm + OFF_WHI);   // reuse dead W region
    if (tid < 128) {
        sPC[tid]       = Wih[v * GG + tid];
        sPC[128 + tid] = Wih[v * GG + 128 + tid];
        sPC[256 + tid] = Wih[v * GG + 256 + tid];
        sPC[384 + tid] = bih[v * GG + tid]       + bhh[v * GG + tid];
        sPC[512 + tid] = bih[v * GG + 128 + tid] + bhh[v * GG + 128 + tid];
        sPC[640 + tid] = bih[v * GG + 256 + tid];
        sPC[768 + tid] = bhh[v * GG + 256 + tid];
    }
    __syncthreads();
    const float wr0 = sPC[j0],      wr1 = sPC[j1];
    const float wz0 = sPC[128+j0],  wz1 = sPC[128+j1];
    const float wn0 = sPC[256+j0],  wn1 = sPC[256+j1];
    const float br0 = sPC[384+j0],  br1 = sPC[384+j1];
    const float bz0 = sPC[512+j0],  bz1 = sPC[512+j1];
    const float bi0 = sPC[640+j0],  bi1 = sPC[640+j1];
    const float bh0c = sPC[768+j0], bh1c = sPC[768+j1];

    const u32 bRd0 = smb + OFF_H + (u32)nrow * 256;    // parity 0
    const u32 bRd1 = bRd0 + 4096;                      // parity 1

    // per-sp chunk-select offsets: lane group bg fetches chunk 4*sp+bg
    u32 cbo[4];
    #pragma unroll
    for (int sp = 0; sp < 4; sp++)
        cbo[sp] = (u32)((((4 * sp + bg) ^ nrow) & 15) << 4);

    // lane's h elements: [0]=(j0,c0) [1]=(j0,c1) [2]=(j1,c0) [3]=(j1,c1)
    float hreg[4] = {0.f, 0.f, 0.f, 0.f};

    for (int t = 0; t < TT; t++) {
        const int p = t & 1;
        const u32 bRd = p ? bRd1 : bRd0;
        char* hw = sm + OFF_H + (p ^ 1) * 4096;

        // ---- hoisted i-gates (depend only on x): overlap their latency with MMA ----
        const float xv0 = sXf[c0 * TT + t];
        const float xv1 = sXf[c1 * TT + t];
        float irv[4], izv[4], inv[4];
        #pragma unroll
        for (int i = 0; i < 4; i++) {
            const int jj = i >> 1;
            const float xv = (i & 1) ? xv1 : xv0;
            irv[i] = fmaf(xv, jj ? wr1 : wr0, jj ? br1 : br0);
            izv[i] = fmaf(xv, jj ? wz1 : wz0, jj ? bz1 : bz0);
            inv[i] = fmaf(xv, jj ? wn1 : wn0, jj ? bi1 : bi0);
        }

        // ---- all B fragments upfront (MLP) ----
        u32 bq[4][4];
        #pragma unroll
        for (int sp = 0; sp < 4; sp++)
            ldsm4(bq[sp][0], bq[sp][1], bq[sp][2], bq[sp][3], bRd + cbo[sp]);

        // ==== gate-major MMA: finish r first, then z, then n ====
        float accrA[4] = {0.f,0.f,0.f,0.f}, accrB[4] = {0.f,0.f,0.f,0.f};
        #pragma unroll
        for (int sp = 0; sp < 4; sp++) {
            mma16816(accrA, ar_h[2*sp],   bq[sp][0], bq[sp][1]);
            mma16816(accrB, ar_h[2*sp+1], bq[sp][2], bq[sp][3]);
        }
        float acczA[4] = {0.f,0.f,0.f,0.f}, acczB[4] = {0.f,0.f,0.f,0.f};
        #pragma unroll
        for (int sp = 0; sp < 4; sp++) {
            mma16816(acczA, az_h[2*sp],   bq[sp][0], bq[sp][1]);
            mma16816(acczB, az_h[2*sp+1], bq[sp][2], bq[sp][3]);
        }
        // sigm(r) overlaps the z/n MMA windows
        float rg[4];
        #pragma unroll
        for (int i = 0; i < 4; i++) rg[i] = sigm_(irv[i] + (accrA[i] + accrB[i]));

        float accnA[4] = {0.f,0.f,0.f,0.f}, accnB[4] = {0.f,0.f,0.f,0.f};
        #pragma unroll
        for (int sp = 0; sp < 4; sp++) {
            mma16816(accnA, an_h[2*sp],   bq[sp][0], bq[sp][1]);
            mma16816(accnB, an_h[2*sp+1], bq[sp][2], bq[sp][3]);
        }
        // sigm(z) overlaps the n MMA window
        float zg[4];
        #pragma unroll
        for (int i = 0; i < 4; i++) zg[i] = sigm_(izv[i] + (acczA[i] + acczB[i]));

        // ---- only tanh(n) + store remain exposed ----
        #pragma unroll
        for (int i = 0; i < 4; i++) {
            const int jj = i >> 1;
            const float bh_ = jj ? bh1c : bh0c;
            float ng = tanha_(inv[i] + rg[i] * ((accnA[i] + accnB[i]) + bh_));
            float hn = fmaf(zg[i], hreg[i] - ng, ng);       // (1-z)*n + z*h
            hreg[i] = hn;
            const int jx = jj ? j1 : j0;
            const int bx = (i & 1) ? c1 : c0;
            *(__half*)(hw + swz(bx, jx)) = __float2half_rn(hn);
        }
        __syncthreads();
    }

    // ============ epilogue: concat[b][v] ============
    float* hfin = (float*)(sm + OFF_X);   // reuse x region: [8][128] f32
    hfin[c0 * HH + j0] = hreg[0];
    hfin[c1 * HH + j0] = hreg[1];
    hfin[c0 * HH + j1] = hreg[2];
    hfin[c1 * HH + j1] = hreg[3];
    __syncthreads();

    {
        const float* Wp_v = Wp + v * HH;
        float s = 0.0f;
        #pragma unroll
        for (int q = 0; q < 4; q++) {
            int jj = L + 32 * q;
            s = fmaf(hfin[w * HH + jj], Wp_v[jj], s);
        }
        #pragma unroll
        for (int off = 16; off; off >>= 1) s += __shfl_xor_sync(0xffffffffu, s, off);
        if (L == 0) g_concat[(b0g + w) * VV + v] = s + bp[v];
    }

    // ============ fused classifier ============
    __syncthreads();
    if (tid == 0) {
        __threadfence();
        atomicAdd(&g_ctr, 1);
    }
    if (blockIdx.x < BB) {
        const int b = blockIdx.x;
        if (tid == 0) {
            while (atomicAdd(&g_ctr, 0) < NCTA) {}
            __threadfence();
        }
        __syncthreads();

        float* sC = (float*)(sm + OFF_X);          // VV floats
        float* sF = (float*)(sm + OFF_X + 256);    // FCN floats
        if (tid < VV) sC[tid] = g_concat[b * VV + tid];
        __syncthreads();

        {
            float a = b1[tid];
            const float* w1 = W1 + tid * VV;
            #pragma unroll
            for (int vv = 0; vv < VV; vv++) a = fmaf(sC[vv], w1[vv], a);
            sF[tid] = fmaxf(a, 0.0f);
        }
        __syncthreads();

        for (int c = w; c < CC; c += 8) {
            const float* w2 = W2 + c * FCN;
            float a = 0.0f;
            #pragma unroll
            for (int q = 0; q < FCN / 32; q++) {
                int f = L + 32 * q;
                a = fmaf(sF[f], w2[f], a);
            }
            #pragma unroll
            for (int off = 16; off; off >>= 1) a += __shfl_xor_sync(0xffffffffu, a, off);
            if (L == 0) out[b * CC + c] = a + b2[c];
        }
        __syncthreads();
        if (tid == 0) {
            int t2 = atomicAdd(&g_ctr2, 1);
            if (t2 == BB - 1) { g_ctr = 0; g_ctr2 = 0; __threadfence(); }
        }
    }
}

extern "C" void kernel_launch(void* const* d_in, const int* in_sizes, int n_in,
                              void* d_out, int out_size)
{
    const float* x   = (const float*)d_in[0];
    const float* Wih = (const float*)d_in[1];
    const float* Whh = (const float*)d_in[2];
    const float* bih = (const float*)d_in[3];
    const float* bhh = (const float*)d_in[4];
    const float* Wp  = (const float*)d_in[5];
    const float* bp  = (const float*)d_in[6];
    const float* W1  = (const float*)d_in[7];
    const float* b1  = (const float*)d_in[8];
    const float* W2  = (const float*)d_in[9];
    const float* b2  = (const float*)d_in[10];
    float* out = (float*)d_out;

    cudaFuncSetAttribute(gru_kernel, cudaFuncAttributeMaxDynamicSharedMemorySize, SMEM_TOT);
    gru_kernel<<<NCTA, NTHR, SMEM_TOT>>>(x, Wih, Whh, bih, bhh, Wp, bp,
                                         W1, b1, W2, b2, out);
}